// round 5
// baseline (speedup 1.0000x reference)
#include <cuda_runtime.h>
#include <cstdint>

#define NN   4096
#define UU   2048
#define RR   5
#define BB   30
#define HH0  500
#define HH1  75
#define EE   262144
#define LDG2 512
#define LDS2 80           // padded d_sums / g2-block stride
#define K1T  16           // GEMM1 k-tiles (K=512)
#define SRD  36           // GEMM1 smem row stride (conflict-free)

// ---------------- scratch (device globals; no allocation allowed) ----------
__device__ float d_W[(size_t)(RR + 1) * NN * HH0];  // block 5 = root (tf32 bits)
__device__ float d_fcp[128 * 512];                  // fc_w tf32, padded [n][k]
__device__ float d_xp[(size_t)NN * NN];             // x tf32 + k-permuted
__device__ float d_VTp[(size_t)LDG2 * NN];          // V^T tf32+perm; row 80r+j; pad rows 0
__device__ float d_g2[(size_t)NN * LDG2];           // g[n][80r+j]
__device__ float d_sums[(size_t)NN * RR * LDS2];
__device__ float d_cnt[NN * RR];
__device__ float d_biasV[HH1];
__device__ int   d_i64flag[2];

// ---------------- small helpers --------------------------------------------
__device__ __forceinline__ uint32_t smem_u32(const void* p) {
    uint32_t a;
    asm("{ .reg .u64 t; cvta.to.shared.u64 t, %1; cvt.u32.u64 %0, t; }"
        : "=r"(a) : "l"(p));
    return a;
}
__device__ __forceinline__ uint32_t f2tf32(float f) {
    uint32_t u;
    asm("cvt.rna.tf32.f32 %0, %1;" : "=r"(u) : "f"(f));
    return u;
}
#define CP_ASYNC16(dst, src) \
    asm volatile("cp.async.cg.shared.global [%0], [%1], 16;" :: "r"(dst), "l"(src))
#define CP_ASYNC16Z(dst, src, sz) \
    asm volatile("cp.async.cg.shared.global [%0], [%1], 16, %2;" :: "r"(dst), "l"(src), "r"(sz))
#define CP_COMMIT() asm volatile("cp.async.commit_group;" ::: "memory")

// ---------------- fused prep: detect + zero + fcp + rootcp + biasV ----------
__global__ void k_prep(const float* __restrict__ root,
                       const float* __restrict__ fc_w,
                       const float* __restrict__ bias,
                       const unsigned int* __restrict__ ei,
                       const unsigned int* __restrict__ et) {
    int idx = blockIdx.x * blockDim.x + threadIdx.x;

    if (idx < NN * LDG2) d_g2[idx] = 0.f;                       // 2,097,152
    if (idx < NN * HH0)                                         // 2,048,000
        d_W[(size_t)RR * NN * HH0 + idx] = __uint_as_float(f2tf32(root[idx]));
    if (idx < NN * RR * LDS2) d_sums[idx] = 0.f;                // 1,638,400
    if (idx < 128 * 512) {                                      // fcp
        int n = idx >> 9, k = idx & 511;
        float v = (n < HH1 && k < HH0) ? fc_w[n * HH0 + k] : 0.f;
        d_fcp[idx] = __uint_as_float(f2tf32(v));
    }
    if (idx < NN * RR) d_cnt[idx] = 0.f;
    if (idx < HH1) {                                            // biasV (serial dot, ILP)
        float s = 0.f;
        const float* fw = fc_w + idx * HH0;
        for (int o = 0; o < HH0; o++) s = fmaf(bias[o], fw[o], s);
        d_biasV[idx] = s;
    }
    if (blockIdx.x == 0 && threadIdx.x < 64) {                  // dtype detect
        int w = threadIdx.x >> 5, lane = threadIdx.x & 31;
        unsigned v = (w == 0) ? ei[2 * lane + 1] : et[2 * lane + 1];
        unsigned b = __ballot_sync(0xFFFFFFFFu, v != 0u);
        if (lane == 0) d_i64flag[w] = (b == 0u);
    }
}

// ---------------- W[r,i,o] = sum_b comp[r,b]*basis[b,i,o]  (tf32-rounded) ---
__global__ void k_buildW(const float* __restrict__ basis,
                         const float* __restrict__ comp) {
    __shared__ float sc[RR * BB];
    if (threadIdx.x < RR * BB) sc[threadIdx.x] = comp[threadIdx.x];
    __syncthreads();
    int idx = blockIdx.x * blockDim.x + threadIdx.x;
    if (idx >= NN * HH0) return;
    float acc[RR] = {0.f, 0.f, 0.f, 0.f, 0.f};
    for (int b = 0; b < BB; b++) {
        float v = basis[(size_t)b * (NN * HH0) + idx];
#pragma unroll
        for (int r = 0; r < RR; r++) acc[r] = fmaf(sc[r * BB + b], v, acc[r]);
    }
    int i = idx / HH0, o = idx - i * HH0;
#pragma unroll
    for (int r = 0; r < RR; r++)
        d_W[((size_t)r * NN + i) * HH0 + o] = __uint_as_float(f2tf32(acc[r]));
}

// ---------------- xp: tf32-round + permute k within 8 ------------------------
__global__ void k_xp(const float* __restrict__ x) {
    int idx = blockIdx.x * blockDim.x + threadIdx.x;
    int row = idx >> 12;
    int kp = idx & 4095;
    int p = kp & 7;
    int sk = (kp & ~7) + (p >> 1) + ((p & 1) << 2);
    reinterpret_cast<uint32_t*>(d_xp)[idx] = f2tf32(x[(size_t)row * NN + sk]);
}

// ---------------- GEMM1 (TC): VTp[80*r+col][kp(i)] = (W @ fc^T)^T ------------
#define STG1_F (2 * 128 * SRD)

__global__ void __launch_bounds__(256, 1) gemm1_mma() {
    extern __shared__ float sm[];
    uint32_t smb = smem_u32(sm);
    int tid = threadIdx.x;
    int lane = tid & 31, wid = tid >> 5;
    int wm = wid & 1, wn = wid >> 1;
    int m0 = blockIdx.y * 128;
    const float* Ag = d_W + (size_t)m0 * HH0;

    float acc[4][4][4];
#pragma unroll
    for (int a = 0; a < 4; a++)
#pragma unroll
        for (int b = 0; b < 4; b++)
#pragma unroll
            for (int d = 0; d < 4; d++) acc[a][b][d] = 0.f;

    auto load_stage = [&](int s, int k0) {
        uint32_t base = smb + (uint32_t)s * (STG1_F * 4);
#pragma unroll
        for (int i = 0; i < 4; i++) {
            int idx = tid + i * 256;
            int row = idx >> 3, seg = idx & 7;
            int k = k0 + seg * 4;
            uint32_t dst = base + row * (SRD * 4) + seg * 16;
            int ok = (k < HH0);
            const float* src = ok ? (Ag + (size_t)row * HH0 + k) : Ag;
            CP_ASYNC16Z(dst, src, ok ? 16 : 0);
        }
#pragma unroll
        for (int i = 0; i < 4; i++) {
            int idx = tid + i * 256;
            int row = idx >> 3, seg = idx & 7;
            uint32_t dst = base + (128 * SRD * 4) + row * (SRD * 4) + seg * 16;
            CP_ASYNC16(dst, d_fcp + (size_t)row * 512 + k0 + seg * 4);
        }
    };

    load_stage(0, 0);  CP_COMMIT();
    load_stage(1, 32); CP_COMMIT();
    load_stage(2, 64); CP_COMMIT();

    const int r = lane >> 2, c = lane & 3;

    for (int kt = 0; kt < K1T; kt++) {
        int s = kt % 3;
        asm volatile("cp.async.wait_group 2;" ::: "memory");
        __syncthreads();
        const float* Asf = sm + (size_t)s * STG1_F;
        const float* Bsf = Asf + 128 * SRD;
#pragma unroll
        for (int ks = 0; ks < 4; ks++) {
            int kb = ks * 8 + c;
            uint32_t a0[4], a1[4], a2[4], a3[4];
#pragma unroll
            for (int mt = 0; mt < 4; mt++) {
                int ro = (wm * 64 + mt * 16 + r) * SRD;
                a0[mt] = __float_as_uint(Asf[ro + kb]);
                a2[mt] = __float_as_uint(Asf[ro + kb + 4]);
                a1[mt] = __float_as_uint(Asf[ro + 8 * SRD + kb]);
                a3[mt] = __float_as_uint(Asf[ro + 8 * SRD + kb + 4]);
            }
#pragma unroll
            for (int nt = 0; nt < 4; nt++) {
                int rn = (wn * 32 + nt * 8 + r) * SRD;
                uint32_t b0 = __float_as_uint(Bsf[rn + kb]);
                uint32_t b1 = __float_as_uint(Bsf[rn + kb + 4]);
#pragma unroll
                for (int mt = 0; mt < 4; mt++) {
                    asm volatile(
                        "mma.sync.aligned.m16n8k8.row.col.f32.tf32.tf32.f32 "
                        "{%0,%1,%2,%3}, {%4,%5,%6,%7}, {%8,%9}, {%0,%1,%2,%3};"
                        : "+f"(acc[mt][nt][0]), "+f"(acc[mt][nt][1]),
                          "+f"(acc[mt][nt][2]), "+f"(acc[mt][nt][3])
                        : "r"(a0[mt]), "r"(a1[mt]), "r"(a2[mt]), "r"(a3[mt]),
                          "r"(b0), "r"(b1));
                }
            }
        }
        __syncthreads();
        if (kt + 3 < K1T) load_stage(s, (kt + 3) * 32);
        CP_COMMIT();
    }

    // epilogue: VTp[(80*r5 + col)][kp(i)] = tf32(acc)
    uint32_t* VT = reinterpret_cast<uint32_t*>(d_VTp);
#pragma unroll
    for (int mt = 0; mt < 4; mt++) {
        int row = m0 + wm * 64 + mt * 16 + r;
        int r5 = row >> 12;
        int i1 = row & 4095;
        int i2 = i1 + 8;
        int kp1 = (i1 & ~7) | ((i1 & 3) << 1) | ((i1 >> 2) & 1);
        int kp2 = (i2 & ~7) | ((i2 & 3) << 1) | ((i2 >> 2) & 1);
#pragma unroll
        for (int nt = 0; nt < 4; nt++) {
            int col = wn * 32 + nt * 8 + 2 * c;
            if (col < HH1) {
                size_t vr = (size_t)(r5 * LDS2 + col) * NN;
                VT[vr + kp1] = f2tf32(acc[mt][nt][0]);
                VT[vr + kp2] = f2tf32(acc[mt][nt][2]);
            }
            if (col + 1 < HH1) {
                size_t vr = (size_t)(r5 * LDS2 + col + 1) * NN;
                VT[vr + kp1] = f2tf32(acc[mt][nt][1]);
                VT[vr + kp2] = f2tf32(acc[mt][nt][3]);
            }
        }
    }
}

// ---------------- GEMM2 (TC): g2 += xp @ VTp^T  (256x128 tile, K-split 2) ---
#define STG_F 12288   // floats/stage: A 8192 + B 4096
#define KT2   64      // ktiles per K-half

__global__ void __launch_bounds__(256, 1) gemm2_mma() {
    extern __shared__ float sm[];
    uint32_t smb = smem_u32(sm);
    int tid = threadIdx.x;
    int lane = tid & 31, wid = tid >> 5;
    int wm = wid & 3, wn = wid >> 2;          // 4 x 2 warps, 64x64 each
    int m0 = blockIdx.y * 256, n0 = blockIdx.x * 128;
    int kbase = blockIdx.z * 2048;
    const float* Ag = d_xp + (size_t)m0 * NN + kbase;
    const float* Bg = d_VTp + (size_t)n0 * NN + kbase;

    float acc[4][8][4];
#pragma unroll
    for (int a = 0; a < 4; a++)
#pragma unroll
        for (int b = 0; b < 8; b++)
#pragma unroll
            for (int d = 0; d < 4; d++) acc[a][b][d] = 0.f;

    auto load_stage = [&](int s, int k0) {
        uint32_t base = smb + (uint32_t)s * (STG_F * 4);
#pragma unroll
        for (int i = 0; i < 8; i++) {       // A: 256 rows x 32
            int idx = tid + i * 256;
            int row = idx >> 3, ks = (idx >> 1) & 3, h = idx & 1;
            uint32_t d = base + row * 128 + ((((uint32_t)(4 * ks)) ^ ((row & 3) << 2)) << 3) + h * 16;
            CP_ASYNC16(d, Ag + (size_t)row * NN + k0 + ks * 8 + h * 4);
        }
#pragma unroll
        for (int i = 0; i < 4; i++) {       // B: 128 rows x 32
            int idx = tid + i * 256;
            int row = idx >> 3, ks = (idx >> 1) & 3, h = idx & 1;
            uint32_t d = base + 32768 + row * 128 + ((((uint32_t)(4 * ks)) ^ ((row & 3) << 2)) << 3) + h * 16;
            CP_ASYNC16(d, Bg + (size_t)row * NN + k0 + ks * 8 + h * 4);
        }
    };

    load_stage(0, 0);  CP_COMMIT();
    load_stage(1, 32); CP_COMMIT();
    load_stage(2, 64); CP_COMMIT();

    const int r = lane >> 2, c = lane & 3;
    const int X = (r & 3) << 2;

    for (int kt = 0; kt < KT2; kt++) {
        int s = kt % 3;
        asm volatile("cp.async.wait_group 2;" ::: "memory");
        __syncthreads();
        const float2* As2 = reinterpret_cast<const float2*>(sm + (size_t)s * STG_F);
        const float2* Bs2 = reinterpret_cast<const float2*>(sm + (size_t)s * STG_F + 8192);
#pragma unroll
        for (int ks = 0; ks < 4; ks++) {
            int sl = (4 * ks) ^ X;
            uint32_t a0[4], a1[4], a2[4], a3[4];
#pragma unroll
            for (int mt = 0; mt < 4; mt++) {
                int row0 = wm * 64 + mt * 16 + r;
                float2 lo = As2[row0 * 16 + sl + c];
                float2 hi = As2[(row0 + 8) * 16 + sl + c];
                a0[mt] = __float_as_uint(lo.x);
                a2[mt] = __float_as_uint(lo.y);
                a1[mt] = __float_as_uint(hi.x);
                a3[mt] = __float_as_uint(hi.y);
            }
#pragma unroll
            for (int nt = 0; nt < 8; nt++) {
                int nrow = wn * 64 + nt * 8 + r;
                float2 bb = Bs2[nrow * 16 + sl + c];
                uint32_t b0 = __float_as_uint(bb.x);
                uint32_t b1 = __float_as_uint(bb.y);
#pragma unroll
                for (int mt = 0; mt < 4; mt++) {
                    asm volatile(
                        "mma.sync.aligned.m16n8k8.row.col.f32.tf32.tf32.f32 "
                        "{%0,%1,%2,%3}, {%4,%5,%6,%7}, {%8,%9}, {%0,%1,%2,%3};"
                        : "+f"(acc[mt][nt][0]), "+f"(acc[mt][nt][1]),
                          "+f"(acc[mt][nt][2]), "+f"(acc[mt][nt][3])
                        : "r"(a0[mt]), "r"(a1[mt]), "r"(a2[mt]), "r"(a3[mt]),
                          "r"(b0), "r"(b1));
                }
            }
        }
        __syncthreads();
        if (kt + 3 < KT2) load_stage(s, (kt + 3) * 32);
        CP_COMMIT();
    }

    // epilogue: atomic add (two K-halves merge)
#pragma unroll
    for (int mt = 0; mt < 4; mt++) {
        int row = m0 + wm * 64 + mt * 16 + r;
#pragma unroll
        for (int nt = 0; nt < 8; nt++) {
            int col = n0 + wn * 64 + nt * 8 + (c << 1);
            asm volatile("red.global.add.v2.f32 [%0], {%1,%2};"
                         :: "l"(&d_g2[(size_t)row * LDG2 + col]),
                            "f"(acc[mt][nt][0]), "f"(acc[mt][nt][1]) : "memory");
            asm volatile("red.global.add.v2.f32 [%0], {%1,%2};"
                         :: "l"(&d_g2[(size_t)(row + 8) * LDG2 + col]),
                            "f"(acc[mt][nt][2]), "f"(acc[mt][nt][3]) : "memory");
        }
    }
}

// ---------------- edge scatter: uniform float4 gather + red.v4 ---------------
__global__ void k_edges(const unsigned int* __restrict__ ei,
                        const unsigned int* __restrict__ et) {
    int e = (blockIdx.x * blockDim.x + threadIdx.x) >> 5;
    int lane = threadIdx.x & 31;
    if (e >= EE) return;
    const int i64e = d_i64flag[0];
    const int i64t = d_i64flag[1];
    long long src, dst, t;
    if (i64e) {
        src = reinterpret_cast<const long long*>(ei)[e];
        dst = reinterpret_cast<const long long*>(ei)[EE + e];
    } else {
        src = reinterpret_cast<const int*>(ei)[e];
        dst = reinterpret_cast<const int*>(ei)[EE + e];
    }
    t = i64t ? reinterpret_cast<const long long*>(et)[e]
             : (long long)reinterpret_cast<const int*>(et)[e];

    const float4* grow = reinterpret_cast<const float4*>(
        d_g2 + (size_t)src * LDG2 + (int)t * LDS2);
    float* srow = d_sums + ((size_t)dst * RR + (size_t)t) * LDS2;
    if (lane < 19) {                 // 76 floats; [75..79] are zero padding
        float4 v = __ldg(grow + lane);
        asm volatile("red.global.add.v4.f32 [%0], {%1,%2,%3,%4};"
                     :: "l"(srow + lane * 4), "f"(v.x), "f"(v.y), "f"(v.z), "f"(v.w)
                     : "memory");
    } else if (lane == 19) {
        atomicAdd(&d_cnt[(int)dst * RR + (int)t], 1.0f);
    }
}

// ---------------- finalize: z -> BN(75) -> relu -> out -----------------------
__global__ void k_final(float* __restrict__ out,
                        const float* __restrict__ gu, const float* __restrict__ bu,
                        const float* __restrict__ gi, const float* __restrict__ bi) {
    int n = blockIdx.x;
    int tid = threadIdx.x;   // 128
    __shared__ float red[128];

    float zval = 0.f;
    if (tid < HH1) {
        float acc = d_biasV[tid] + d_g2[(size_t)n * LDG2 + RR * LDS2 + tid];
#pragma unroll
        for (int r = 0; r < RR; r++) {
            float c = d_cnt[n * RR + r];
            acc += d_sums[((size_t)(n * RR + r)) * LDS2 + tid] / fmaxf(c, 1.0f);
        }
        zval = acc;
    }
    red[tid] = zval;
    __syncthreads();
#pragma unroll
    for (int s = 64; s > 0; s >>= 1) {
        if (tid < s) red[tid] += red[tid + s];
        __syncthreads();
    }
    float mu = red[0] * (1.0f / HH1);
    __syncthreads();
    float d = (tid < HH1) ? (zval - mu) : 0.f;
    red[tid] = d * d;
    __syncthreads();
#pragma unroll
    for (int s = 64; s > 0; s >>= 1) {
        if (tid < s) red[tid] += red[tid + s];
        __syncthreads();
    }
    float var = red[0] * (1.0f / HH1);

    float gamma, beta;
    if (n < UU) { gamma = gu[n]; beta = bu[n]; }
    else        { gamma = gi[n - UU]; beta = bi[n - UU]; }

    if (tid < HH1) {
        float y = gamma * (zval - mu) * rsqrtf(var + 1e-5f) + beta;
        out[(size_t)n * HH1 + tid] = fmaxf(y, 0.f);
    }
}

// ---------------- launch ------------------------------------------------------
extern "C" void kernel_launch(void* const* d_in, const int* in_sizes, int n_in,
                              void* d_out, int out_size) {
    const float* x     = (const float*)d_in[0];
    const float* basis = (const float*)d_in[1];
    const float* comp  = (const float*)d_in[2];
    const float* root  = (const float*)d_in[3];
    const float* bias  = (const float*)d_in[4];
    const float* fc_w  = (const float*)d_in[5];
    const float* gu    = (const float*)d_in[6];
    const float* bu    = (const float*)d_in[7];
    const float* gi    = (const float*)d_in[8];
    const float* bi    = (const float*)d_in[9];
    const unsigned int* ei = (const unsigned int*)d_in[10];
    const unsigned int* et = (const unsigned int*)d_in[11];
    float* out = (float*)d_out;

    static int smem_set = 0;
    if (!smem_set) {
        cudaFuncSetAttribute(gemm2_mma, cudaFuncAttributeMaxDynamicSharedMemorySize,
                             3 * STG_F * 4);
        cudaFuncSetAttribute(gemm1_mma, cudaFuncAttributeMaxDynamicSharedMemorySize,
                             3 * STG1_F * 4);
        smem_set = 1;
    }

    k_prep<<<(NN * LDG2) / 256, 256>>>(root, fc_w, bias, ei, et);
    k_buildW<<<(NN * HH0) / 256, 256>>>(basis, comp);
    k_xp<<<(NN * NN) / 256, 256>>>(x);

    // GEMM1 (TC): VTp = (W[6 blocks] @ fc^T)^T, fused transpose+tf32+permute
    gemm1_mma<<<dim3(1, (RR + 1) * NN / 128), 256, 3 * STG1_F * 4>>>();

    // GEMM2 (TC): g2 += xp @ VTp^T  (M=4096, N=512, K=4096, K-split 2)
    gemm2_mma<<<dim3(4, 16, 2), 256, 3 * STG_F * 4>>>();

    k_edges<<<EE / 8, 256>>>(ei, et);
    k_final<<<NN, 128>>>(out, gu, bu, gi, bi);
}

// round 6
// speedup vs baseline: 1.0301x; 1.0301x over previous
#include <cuda_runtime.h>
#include <cstdint>

#define NN   4096
#define UU   2048
#define RR   5
#define BB   30
#define HH0  500
#define HH1  75
#define EE   262144
#define LDG2 512
#define LDS2 80           // padded d_sums / g2-block stride
#define KT   128          // GEMM2 k-tiles
#define KPT  16           // gemmP k-tiles (K=512)
#define SRD  36           // gemmP A smem row stride (conflict-free)
#define MTOT (31 * NN)    // 30 basis blocks + root

// ---------------- scratch (device globals; no allocation allowed) ----------
__device__ float d_fcp[128 * 512];                  // fc_w tf32, k-permuted [n][kp]
__device__ float d_xp[(size_t)NN * NN];             // x tf32 + k-permuted
__device__ float d_Pt[(size_t)31 * LDS2 * NN];      // Pt[b*80+j][i]
__device__ float d_VTp[(size_t)LDG2 * NN];          // V^T tf32+perm; row 80r+j; pad rows 0
__device__ float d_g2[(size_t)NN * LDG2];           // g[n][80r+j]
__device__ float d_sums[(size_t)NN * RR * LDS2];
__device__ float d_cnt[NN * RR];
__device__ float d_biasV[HH1];
__device__ int   d_i64flag[2];

// ---------------- small helpers --------------------------------------------
__device__ __forceinline__ uint32_t smem_u32(const void* p) {
    uint32_t a;
    asm("{ .reg .u64 t; cvta.to.shared.u64 t, %1; cvt.u32.u64 %0, t; }"
        : "=r"(a) : "l"(p));
    return a;
}
__device__ __forceinline__ uint32_t f2tf32(float f) {
    uint32_t u;
    asm("cvt.rna.tf32.f32 %0, %1;" : "=r"(u) : "f"(f));
    return u;
}
#define CP_ASYNC16(dst, src) \
    asm volatile("cp.async.cg.shared.global [%0], [%1], 16;" :: "r"(dst), "l"(src))
#define CP_ASYNC16Z(dst, src, sz) \
    asm volatile("cp.async.cg.shared.global [%0], [%1], 16, %2;" :: "r"(dst), "l"(src), "r"(sz))
#define CP_COMMIT() asm volatile("cp.async.commit_group;" ::: "memory")

// ---------------- fused prep: detect + zero + fcp(perm) + biasV --------------
__global__ void k_prep(const float* __restrict__ fc_w,
                       const float* __restrict__ bias,
                       const unsigned int* __restrict__ ei,
                       const unsigned int* __restrict__ et) {
    int idx = blockIdx.x * blockDim.x + threadIdx.x;

    if (idx < NN * RR * LDS2) d_sums[idx] = 0.f;                // 1,638,400
    if (idx < 128 * 512) {                                      // fcp, k-permuted
        int n = idx >> 9, kp = idx & 511;
        int p = kp & 7;
        int sk = (kp & ~7) + (p >> 1) + ((p & 1) << 2);
        float v = (n < HH1 && sk < HH0) ? fc_w[n * HH0 + sk] : 0.f;
        d_fcp[idx] = __uint_as_float(f2tf32(v));
    }
    if (idx < NN * RR) d_cnt[idx] = 0.f;
    if (idx < HH1) {                                            // biasV
        float s = 0.f;
        const float* fw = fc_w + idx * HH0;
        for (int o = 0; o < HH0; o++) s = fmaf(bias[o], fw[o], s);
        d_biasV[idx] = s;
    }
    if (blockIdx.x == 0 && threadIdx.x < 64) {                  // dtype detect
        int w = threadIdx.x >> 5, lane = threadIdx.x & 31;
        unsigned v = (w == 0) ? ei[2 * lane + 1] : et[2 * lane + 1];
        unsigned b = __ballot_sync(0xFFFFFFFFu, v != 0u);
        if (lane == 0) d_i64flag[w] = (b == 0u);
    }
}

// ---------------- xp: tf32-round + permute k within 8 ------------------------
__global__ void k_xp(const float* __restrict__ x) {
    int idx = blockIdx.x * blockDim.x + threadIdx.x;
    int row = idx >> 12;
    int kp = idx & 4095;
    int p = kp & 7;
    int sk = (kp & ~7) + (p >> 1) + ((p & 1) << 2);
    reinterpret_cast<uint32_t*>(d_xp)[idx] = f2tf32(x[(size_t)row * NN + sk]);
}

// ---------------- gemmP (TC): Pt = ([basis;root] @ fc^T), M=126976 -----------
// CTA 128x128, 8 warps of 64x32, 3-stage cp.async, 2 CTAs/SM.
// A unswizzled stride-36 smem (scalar LDS, conflict-free); B = permuted fcp
// in gemm2-style swizzled layout (float2 LDS).
#define STGP_F (128 * SRD + 128 * 32)   // 4608 + 4096 floats per stage

__global__ void __launch_bounds__(256, 2) gemmP(const float* __restrict__ basis,
                                                const float* __restrict__ root) {
    extern __shared__ float sm[];
    uint32_t smb = smem_u32(sm);
    int tid = threadIdx.x;
    int lane = tid & 31, wid = tid >> 5;
    int wm = wid & 1, wn = wid >> 1;
    int m0 = blockIdx.y * 128;
    const float* Ag = (m0 < 30 * NN) ? (basis + (size_t)m0 * HH0)
                                     : (root + (size_t)(m0 - 30 * NN) * HH0);

    float acc[4][4][4];
#pragma unroll
    for (int a = 0; a < 4; a++)
#pragma unroll
        for (int b = 0; b < 4; b++)
#pragma unroll
            for (int d = 0; d < 4; d++) acc[a][b][d] = 0.f;

    auto load_stage = [&](int s, int k0) {
        uint32_t base = smb + (uint32_t)s * (STGP_F * 4);
#pragma unroll
        for (int i = 0; i < 4; i++) {        // A: 128 rows x 32 floats, stride 36
            int idx = tid + i * 256;
            int row = idx >> 3, seg = idx & 7;
            int k = k0 + seg * 4;
            uint32_t dst = base + row * (SRD * 4) + seg * 16;
            int ok = (k < HH0);
            const float* src = ok ? (Ag + (size_t)row * HH0 + k) : Ag;
            CP_ASYNC16Z(dst, src, ok ? 16 : 0);
        }
#pragma unroll
        for (int i = 0; i < 4; i++) {        // B: 128 rows x 32, swizzled
            int idx = tid + i * 256;
            int row = idx >> 3, ks = (idx >> 1) & 3, h = idx & 1;
            uint32_t d = base + (128 * SRD * 4) + row * 128 +
                         ((((uint32_t)(4 * ks)) ^ ((row & 3) << 2)) << 3) + h * 16;
            CP_ASYNC16(d, d_fcp + (size_t)row * 512 + k0 + ks * 8 + h * 4);
        }
    };

    load_stage(0, 0);  CP_COMMIT();
    load_stage(1, 32); CP_COMMIT();
    load_stage(2, 64); CP_COMMIT();

    const int r = lane >> 2, c = lane & 3;
    const int X = (r & 3) << 2;

    for (int kt = 0; kt < KPT; kt++) {
        int s = kt % 3;
        asm volatile("cp.async.wait_group 2;" ::: "memory");
        __syncthreads();
        const float* Asf = sm + (size_t)s * STGP_F;
        const float2* Bs2 = reinterpret_cast<const float2*>(Asf + 128 * SRD);
#pragma unroll
        for (int ks = 0; ks < 4; ks++) {
            int kb = ks * 8 + c;
            int sl = (4 * ks) ^ X;
            uint32_t a0[4], a1[4], a2[4], a3[4];
#pragma unroll
            for (int mt = 0; mt < 4; mt++) {
                int ro = (wm * 64 + mt * 16 + r) * SRD;
                a0[mt] = __float_as_uint(Asf[ro + kb]);
                a2[mt] = __float_as_uint(Asf[ro + kb + 4]);
                a1[mt] = __float_as_uint(Asf[ro + 8 * SRD + kb]);
                a3[mt] = __float_as_uint(Asf[ro + 8 * SRD + kb + 4]);
            }
#pragma unroll
            for (int nt = 0; nt < 4; nt++) {
                int nrow = wn * 32 + nt * 8 + r;
                float2 bb = Bs2[nrow * 16 + sl + c];
                uint32_t b0 = __float_as_uint(bb.x);
                uint32_t b1 = __float_as_uint(bb.y);
#pragma unroll
                for (int mt = 0; mt < 4; mt++) {
                    asm volatile(
                        "mma.sync.aligned.m16n8k8.row.col.f32.tf32.tf32.f32 "
                        "{%0,%1,%2,%3}, {%4,%5,%6,%7}, {%8,%9}, {%0,%1,%2,%3};"
                        : "+f"(acc[mt][nt][0]), "+f"(acc[mt][nt][1]),
                          "+f"(acc[mt][nt][2]), "+f"(acc[mt][nt][3])
                        : "r"(a0[mt]), "r"(a1[mt]), "r"(a2[mt]), "r"(a3[mt]),
                          "r"(b0), "r"(b1));
                }
            }
        }
        __syncthreads();
        if (kt + 3 < KPT) load_stage(s, (kt + 3) * 32);
        CP_COMMIT();
    }

    // epilogue: Pt[(b*80 + col)][i] = acc (fp32)
    int bblk = m0 >> 12;
#pragma unroll
    for (int mt = 0; mt < 4; mt++) {
        int m = m0 + wm * 64 + mt * 16 + r;
        int i1 = m & 4095;
#pragma unroll
        for (int nt = 0; nt < 4; nt++) {
            int col = wn * 32 + nt * 8 + 2 * c;
            if (col < HH1) {
                size_t pr = (size_t)(bblk * LDS2 + col) * NN;
                d_Pt[pr + i1] = acc[mt][nt][0];
                d_Pt[pr + i1 + 8] = acc[mt][nt][2];
            }
            if (col + 1 < HH1) {
                size_t pr = (size_t)(bblk * LDS2 + col + 1) * NN;
                d_Pt[pr + i1] = acc[mt][nt][1];
                d_Pt[pr + i1 + 8] = acc[mt][nt][3];
            }
        }
    }
}

// ---------------- combine: VTp[80r+j][kp(i)] = sum_b comp[r,b] Pt[b*80+j][i] -
__global__ void k_combine(const float* __restrict__ comp) {
    __shared__ float sc[RR * BB];
    if (threadIdx.x < RR * BB) sc[threadIdx.x] = comp[threadIdx.x];
    __syncthreads();
    int idx = blockIdx.x * blockDim.x + threadIdx.x;   // over 75*4096
    int j = idx >> 12, i = idx & 4095;

    float s[RR] = {0.f, 0.f, 0.f, 0.f, 0.f};
#pragma unroll 5
    for (int b = 0; b < BB; b++) {
        float p = d_Pt[((size_t)(b * LDS2 + j) << 12) + i];
#pragma unroll
        for (int r = 0; r < RR; r++) s[r] = fmaf(sc[r * BB + b], p, s[r]);
    }
    int kp = (i & ~7) | ((i & 3) << 1) | ((i >> 2) & 1);
    uint32_t* VT = reinterpret_cast<uint32_t*>(d_VTp);
#pragma unroll
    for (int r = 0; r < RR; r++)
        VT[((size_t)(r * LDS2 + j) << 12) + kp] = f2tf32(s[r]);
    VT[((size_t)(RR * LDS2 + j) << 12) + kp] =
        f2tf32(d_Pt[((size_t)(30 * LDS2 + j) << 12) + i]);
}

// ---------------- GEMM2 (TC): g2 = xp @ VTp^T  (128x128, direct store) ------
#define STG_F 8192   // floats per stage (A 4096 + B 4096)

__global__ void __launch_bounds__(256, 1) gemm2_mma() {
    extern __shared__ float sm[];
    uint32_t smb = smem_u32(sm);
    int tid = threadIdx.x;
    int lane = tid & 31, wid = tid >> 5;
    int wm = wid & 1, wn = wid >> 1;
    int m0 = blockIdx.y * 128, n0 = blockIdx.x * 128;
    const float* Ag = d_xp + (size_t)m0 * NN;
    const float* Bg = d_VTp + (size_t)n0 * NN;

    float acc[4][4][4];
#pragma unroll
    for (int a = 0; a < 4; a++)
#pragma unroll
        for (int b = 0; b < 4; b++)
#pragma unroll
            for (int d = 0; d < 4; d++) acc[a][b][d] = 0.f;

    auto load_stage = [&](int s, int k0) {
        uint32_t base = smb + (uint32_t)s * (STG_F * 4);
#pragma unroll
        for (int i = 0; i < 4; i++) {
            int idx = tid + i * 256;
            int row = idx >> 3, ks = (idx >> 1) & 3, h = idx & 1;
            uint32_t d = base + row * 128 + ((((uint32_t)(4 * ks)) ^ ((row & 3) << 2)) << 3) + h * 16;
            CP_ASYNC16(d, Ag + (size_t)row * NN + k0 + ks * 8 + h * 4);
        }
#pragma unroll
        for (int i = 0; i < 4; i++) {
            int idx = tid + i * 256;
            int row = idx >> 3, ks = (idx >> 1) & 3, h = idx & 1;
            uint32_t d = base + 16384 + row * 128 + ((((uint32_t)(4 * ks)) ^ ((row & 3) << 2)) << 3) + h * 16;
            CP_ASYNC16(d, Bg + (size_t)row * NN + k0 + ks * 8 + h * 4);
        }
    };

    load_stage(0, 0);  CP_COMMIT();
    load_stage(1, 32); CP_COMMIT();
    load_stage(2, 64); CP_COMMIT();

    const int r = lane >> 2, c = lane & 3;
    const int X = (r & 3) << 2;

    for (int kt = 0; kt < KT; kt++) {
        int s = kt % 3;
        asm volatile("cp.async.wait_group 2;" ::: "memory");
        __syncthreads();
        const float2* As2 = reinterpret_cast<const float2*>(sm + (size_t)s * STG_F);
        const float2* Bs2 = reinterpret_cast<const float2*>(sm + (size_t)s * STG_F + 4096);
#pragma unroll
        for (int ks = 0; ks < 4; ks++) {
            int sl = (4 * ks) ^ X;
            uint32_t a0[4], a1[4], a2[4], a3[4];
#pragma unroll
            for (int mt = 0; mt < 4; mt++) {
                int row0 = wm * 64 + mt * 16 + r;
                float2 lo = As2[row0 * 16 + sl + c];
                float2 hi = As2[(row0 + 8) * 16 + sl + c];
                a0[mt] = __float_as_uint(lo.x);
                a2[mt] = __float_as_uint(lo.y);
                a1[mt] = __float_as_uint(hi.x);
                a3[mt] = __float_as_uint(hi.y);
            }
#pragma unroll
            for (int nt = 0; nt < 4; nt++) {
                int nrow = wn * 32 + nt * 8 + r;
                float2 bb = Bs2[nrow * 16 + sl + c];
                uint32_t b0 = __float_as_uint(bb.x);
                uint32_t b1 = __float_as_uint(bb.y);
#pragma unroll
                for (int mt = 0; mt < 4; mt++) {
                    asm volatile(
                        "mma.sync.aligned.m16n8k8.row.col.f32.tf32.tf32.f32 "
                        "{%0,%1,%2,%3}, {%4,%5,%6,%7}, {%8,%9}, {%0,%1,%2,%3};"
                        : "+f"(acc[mt][nt][0]), "+f"(acc[mt][nt][1]),
                          "+f"(acc[mt][nt][2]), "+f"(acc[mt][nt][3])
                        : "r"(a0[mt]), "r"(a1[mt]), "r"(a2[mt]), "r"(a3[mt]),
                          "r"(b0), "r"(b1));
                }
            }
        }
        __syncthreads();
        if (kt + 3 < KT) load_stage(s, (kt + 3) * 32);
        CP_COMMIT();
    }

#pragma unroll
    for (int mt = 0; mt < 4; mt++) {
        int row = m0 + wm * 64 + mt * 16 + r;
#pragma unroll
        for (int nt = 0; nt < 4; nt++) {
            int col = n0 + wn * 32 + nt * 8 + (c << 1);
            *reinterpret_cast<float2*>(&d_g2[(size_t)row * LDG2 + col]) =
                make_float2(acc[mt][nt][0], acc[mt][nt][1]);
            *reinterpret_cast<float2*>(&d_g2[(size_t)(row + 8) * LDG2 + col]) =
                make_float2(acc[mt][nt][2], acc[mt][nt][3]);
        }
    }
}

// ---------------- edge scatter: uniform float4 gather + red.v4 ---------------
__global__ void k_edges(const unsigned int* __restrict__ ei,
                        const unsigned int* __restrict__ et) {
    int e = (blockIdx.x * blockDim.x + threadIdx.x) >> 5;
    int lane = threadIdx.x & 31;
    if (e >= EE) return;
    const int i64e = d_i64flag[0];
    const int i64t = d_i64flag[1];
    long long src, dst, t;
    if (i64e) {
        src = reinterpret_cast<const long long*>(ei)[e];
        dst = reinterpret_cast<const long long*>(ei)[EE + e];
    } else {
        src = reinterpret_cast<const int*>(ei)[e];
        dst = reinterpret_cast<const int*>(ei)[EE + e];
    }
    t = i64t ? reinterpret_cast<const long long*>(et)[e]
             : (long long)reinterpret_cast<const int*>(et)[e];

    const float4* grow = reinterpret_cast<const float4*>(
        d_g2 + (size_t)src * LDG2 + (int)t * LDS2);
    float* srow = d_sums + ((size_t)dst * RR + (size_t)t) * LDS2;
    if (lane < 19) {                 // 76 floats; [75..79] are zero padding
        float4 v = __ldg(grow + lane);
        asm volatile("red.global.add.v4.f32 [%0], {%1,%2,%3,%4};"
                     :: "l"(srow + lane * 4), "f"(v.x), "f"(v.y), "f"(v.z), "f"(v.w)
                     : "memory");
    } else if (lane == 19) {
        atomicAdd(&d_cnt[(int)dst * RR + (int)t], 1.0f);
    }
}

// ---------------- finalize: z -> BN(75) -> relu -> out -----------------------
__global__ void k_final(float* __restrict__ out,
                        const float* __restrict__ gu, const float* __restrict__ bu,
                        const float* __restrict__ gi, const float* __restrict__ bi) {
    int n = blockIdx.x;
    int tid = threadIdx.x;   // 128
    __shared__ float red[128];

    float zval = 0.f;
    if (tid < HH1) {
        float acc = d_biasV[tid] + d_g2[(size_t)n * LDG2 + RR * LDS2 + tid];
#pragma unroll
        for (int r = 0; r < RR; r++) {
            float c = d_cnt[n * RR + r];
            acc += d_sums[((size_t)(n * RR + r)) * LDS2 + tid] / fmaxf(c, 1.0f);
        }
        zval = acc;
    }
    red[tid] = zval;
    __syncthreads();
#pragma unroll
    for (int s = 64; s > 0; s >>= 1) {
        if (tid < s) red[tid] += red[tid + s];
        __syncthreads();
    }
    float mu = red[0] * (1.0f / HH1);
    __syncthreads();
    float d = (tid < HH1) ? (zval - mu) : 0.f;
    red[tid] = d * d;
    __syncthreads();
#pragma unroll
    for (int s = 64; s > 0; s >>= 1) {
        if (tid < s) red[tid] += red[tid + s];
        __syncthreads();
    }
    float var = red[0] * (1.0f / HH1);

    float gamma, beta;
    if (n < UU) { gamma = gu[n]; beta = bu[n]; }
    else        { gamma = gi[n - UU]; beta = bi[n - UU]; }

    if (tid < HH1) {
        float y = gamma * (zval - mu) * rsqrtf(var + 1e-5f) + beta;
        out[(size_t)n * HH1 + tid] = fmaxf(y, 0.f);
    }
}

// ---------------- launch ------------------------------------------------------
extern "C" void kernel_launch(void* const* d_in, const int* in_sizes, int n_in,
                              void* d_out, int out_size) {
    const float* x     = (const float*)d_in[0];
    const float* basis = (const float*)d_in[1];
    const float* comp  = (const float*)d_in[2];
    const float* root  = (const float*)d_in[3];
    const float* bias  = (const float*)d_in[4];
    const float* fc_w  = (const float*)d_in[5];
    const float* gu    = (const float*)d_in[6];
    const float* bu    = (const float*)d_in[7];
    const float* gi    = (const float*)d_in[8];
    const float* bi    = (const float*)d_in[9];
    const unsigned int* ei = (const unsigned int*)d_in[10];
    const unsigned int* et = (const unsigned int*)d_in[11];
    float* out = (float*)d_out;

    static int smem_set = 0;
    if (!smem_set) {
        cudaFuncSetAttribute(gemm2_mma, cudaFuncAttributeMaxDynamicSharedMemorySize,
                             3 * STG_F * 4);
        cudaFuncSetAttribute(gemmP, cudaFuncAttributeMaxDynamicSharedMemorySize,
                             3 * STGP_F * 4);
        smem_set = 1;
    }

    k_prep<<<(NN * RR * LDS2) / 256, 256>>>(fc_w, bias, ei, et);
    k_xp<<<(NN * NN) / 256, 256>>>(x);

    // gemmP (TC): Pt = [basis; root] @ fc^T   (M=126976, K=512, N=128)
    gemmP<<<dim3(1, MTOT / 128), 256, 3 * STGP_F * 4>>>(basis, root);

    // combine: VTp = comp-weighted sum of Pt blocks (+ root), tf32 + permute
    k_combine<<<(HH1 * NN) / 256, 256>>>(comp);

    // GEMM2 (TC): g2 = xp @ VTp^T   (M=4096, N=512, K=4096)
    gemm2_mma<<<dim3(4, 32), 256, 3 * STG_F * 4>>>();

    k_edges<<<EE / 8, 256>>>(ei, et);
    k_final<<<NN, 128>>>(out, gu, bu, gi, bi);
}